// round 14
// baseline (speedup 1.0000x reference)
#include <cuda_runtime.h>

// PatchChamferDistance: B=32, G=64, P=256, D=3 (fp32)
// R14: joint scan v3 — each pair computed ONCE (halves fma2 vs R12's wall).
// 256-thr CTA = 1 patch. lane rg owns rows [8rg,8rg+8); warp cg owns cols
// [32cg,32cg+32). t_ij = d2_ij + C computed by 4 pair-packed fma2 chains;
// rowmin -> rmn[8] regs; colmin -> 8-row tree + ONE xor-1 shuffle + 1 STS
// per column into colsm[warp][col][16]; epilogue finishes both mins from smem.

#define BGQ  2048
#define NP   256
#define T    256
#define BIAS 128.0f
#define POSINF_BITS 0x7F800000

typedef unsigned long long u64;

__device__ float    g_accum;
__device__ unsigned g_count;

__device__ __forceinline__ u64 pk2(float a, float b) {
    u64 r;
    asm("mov.b64 %0, {%1, %2};" : "=l"(r) : "f"(a), "f"(b));
    return r;
}
__device__ __forceinline__ u64 fma2(u64 a, u64 b, u64 c) {
    u64 d;
    asm("fma.rn.f32x2 %0, %1, %2, %3;" : "=l"(d) : "l"(a), "l"(b), "l"(c));
    return d;
}
__device__ __forceinline__ u64 add2(u64 a, u64 b) {
    u64 d;
    asm("add.rn.f32x2 %0, %1, %2;" : "=l"(d) : "l"(a), "l"(b));
    return d;
}
__device__ __forceinline__ void upk2i(u64 v, int& lo, int& hi) {
    asm("mov.b64 {%0, %1}, %2;" : "=r"(lo), "=r"(hi) : "l"(v));
}

__global__ __launch_bounds__(T)
void pcd_chamfer_kernel(const float* __restrict__ pred,
                        const float* __restrict__ tgt,
                        float* __restrict__ out)
{
    __shared__ float4     srow[NP];          // pred rows {x,y,z,w}
    __shared__ ulonglong2 scA[NP];           // tgt: {-2x,-2x,-2y,-2y}
    __shared__ ulonglong2 scB[NP];           // tgt: {-2z,-2z, w+C, w+C}
    __shared__ int        colsm[8][32][20];  // [warp][col][16 slots + pad]
    __shared__ int        rowpart[8][NP];    // per-warp rowmin partials
    __shared__ float      wsum[T / 32];

    const int t     = threadIdx.x;
    const int patch = blockIdx.x;

    const float* pb = pred + (size_t)patch * NP * 3;
    const float* qb = tgt  + (size_t)patch * NP * 3;

    // phase 1: cooperative load, 1 point of each cloud per thread
    {
        float x = pb[t * 3 + 0], y = pb[t * 3 + 1], z = pb[t * 3 + 2];
        srow[t] = make_float4(x, y, z, x * x + y * y + z * z);

        x = qb[t * 3 + 0]; y = qb[t * 3 + 1]; z = qb[t * 3 + 2];
        float w = x * x + y * y + z * z;
        scA[t] = make_ulonglong2(pk2(-2.f * x, -2.f * x), pk2(-2.f * y, -2.f * y));
        scB[t] = make_ulonglong2(pk2(-2.f * z, -2.f * z), pk2(w + BIAS, w + BIAS));
    }
    __syncthreads();

    const int rg = t & 31;     // lane -> rows [8rg, 8rg+8)
    const int cg = t >> 5;     // warp -> cols [32cg, 32cg+32)

    // own 8 pred rows, packed pairwise
    u64 X2[4], Y2[4], Z2[4], W2[4];
#pragma unroll
    for (int k = 0; k < 4; k++) {
        float4 r0 = srow[8 * rg + 2 * k];
        float4 r1 = srow[8 * rg + 2 * k + 1];
        X2[k] = pk2(r0.x, r1.x);
        Y2[k] = pk2(r0.y, r1.y);
        Z2[k] = pk2(r0.z, r1.z);
        W2[k] = pk2(r0.w, r1.w);   // {pw0, pw1}
    }

    int rmn[8];
#pragma unroll
    for (int r = 0; r < 8; r++) rmn[r] = POSINF_BITS;

    const int c0 = cg * 32;

#pragma unroll 4
    for (int jc = 0; jc < 32; jc++) {
        ulonglong2 a = scA[c0 + jc];   // warp-uniform -> LDS broadcast
        ulonglong2 b = scB[c0 + jc];

        // t2 = {pw + qw + C - 2 dot} = {d2 + C}  (always > 0)
        int d[8];
#pragma unroll
        for (int k = 0; k < 4; k++) {
            u64 seed = add2(W2[k], b.y);          // early, off the LDS
            u64 acc  = fma2(X2[k], a.x, seed);
            acc = fma2(Y2[k], a.y, acc);
            acc = fma2(Z2[k], b.x, acc);
            upk2i(acc, d[2 * k], d[2 * k + 1]);   // raw bits, int order == float order
        }

        // rowmin updates (8 IMNMX, alu)
#pragma unroll
        for (int r = 0; r < 8; r++)
            rmn[r] = min(rmn[r], d[r]);

        // colmin: tree over own 8 rows (7 IMNMX) ...
        int m = min(min(min(d[0], d[1]), min(d[2], d[3])),
                    min(min(d[4], d[5]), min(d[6], d[7])));
        // ... one xor-1 stage (32 -> 16 partials), then straight to smem
        m = min(m, __shfl_xor_sync(0xffffffffu, m, 1));
        colsm[cg][jc][rg >> 1] = m;    // lanes 2s,2s+1 write same value: benign
    }

    // rowmin partials -> smem
#pragma unroll
    for (int r = 0; r < 8; r++)
        rowpart[cg][8 * rg + r] = rmn[r];
    __syncthreads();

    // ---- epilogue: finish both mins, once per thread ----
    float v = 0.f;
    {   // column t: min of its 16 smem partials
        const int* cp = colsm[t >> 5][t & 31];
        int m = cp[0];
#pragma unroll
        for (int i = 1; i < 16; i++) m = min(m, cp[i]);
        v += fmaxf(__int_as_float(m) - BIAS, 0.f);
    }
    {   // row t: min across the 8 warps' partials
        int m = rowpart[0][t];
#pragma unroll
        for (int w = 1; w < 8; w++) m = min(m, rowpart[w][t]);
        v += fmaxf(__int_as_float(m) - BIAS, 0.f);
    }

    // block reduction
#pragma unroll
    for (int o = 16; o > 0; o >>= 1)
        v += __shfl_down_sync(0xffffffffu, v, o);
    if ((t & 31) == 0) wsum[t >> 5] = v;
    __syncthreads();

    // last-CTA pattern: single launch, no zero kernel
    if (t == 0) {
        float s = 0.f;
#pragma unroll
        for (int w = 0; w < T / 32; w++) s += wsum[w];
        atomicAdd(&g_accum, s);
        __threadfence();
        unsigned done = atomicAdd(&g_count, 1u);
        if (done == (unsigned)(gridDim.x - 1)) {
            __threadfence();
            float total = *((volatile float*)&g_accum);
            out[0] = total * (1.0f / ((float)NP * (float)BGQ));
            g_accum = 0.f;
            __threadfence();
            g_count = 0u;
        }
    }
}

extern "C" void kernel_launch(void* const* d_in, const int* in_sizes, int n_in,
                              void* d_out, int out_size)
{
    const float* pred = (const float*)d_in[0];
    const float* tgt  = (const float*)d_in[1];
    float* out = (float*)d_out;

    pcd_chamfer_kernel<<<BGQ, T>>>(pred, tgt, out);
}